// round 1
// baseline (speedup 1.0000x reference)
#include <cuda_runtime.h>
#include <cuda_bf16.h>
#include <math_constants.h>

// Problem constants
#define BB   16
#define T1C  512
#define T2C  64
#define DC   768
#define HC   12
#define EC   64
#define TKC  576            // T1 + T2
#define SCALE_P 0.3535533905932738f   // 64^-0.25

// ---------------- scratch (device globals; no allocation allowed) ----------------
__device__ float g_projF[6ULL * BB * T1C * DC];   // [6][B][T1][D]
__device__ float g_projI[6ULL * BB * T2C * DC];   // [6][B][T2][D]
__device__ float g_attV [(size_t)BB * T1C * DC];  // [B][T1][D]
__device__ float g_attL [(size_t)BB * T2C * DC];  // [B][T2][D]
__device__ float g_maskF[BB * TKC];               // 1.0 = masked (-> -1e9), 0.0 = keep

// ---------------- mask dtype detection + materialization ----------------
// att_mask is a bool array [B,1,1,576]; marshalled dtype is ambiguous (u8/i32/f32).
// Classify the raw buffer encoding, then write float 0/1 mask.
__global__ void mask_prep_kernel(const unsigned* __restrict__ raw, float* __restrict__ mf)
{
    __shared__ int flags[2];   // [0]=notInt32, [1]=notU8
    int tid = threadIdx.x;
    if (tid < 2) flags[tid] = 0;
    __syncthreads();

    int notInt = 0, notU8 = 0;
    const int nWords = (BB * TKC) / 4;   // 2304 words = 9216 bytes (valid in all encodings)
    for (int i = tid; i < nWords; i += blockDim.x) {
        unsigned w = raw[i];
        if (w > 1u) notInt = 1;
        if (w & 0xFEFEFEFEu) notU8 = 1;
    }
    if (notInt) atomicOr(&flags[0], 1);
    if (notU8)  atomicOr(&flags[1], 1);
    __syncthreads();

    int mode;                 // 0 = int32, 1 = uint8, 2 = float32
    if (!flags[0]) mode = 0;  // all words in {0,1} -> int32
    else if (!flags[1]) mode = 1;  // all bytes in {0,1} -> uint8
    else mode = 2;            // else float32 (0.0 / 1.0)

    for (int i = tid; i < BB * TKC; i += blockDim.x) {
        float v;
        if (mode == 0)      v = ((const int*)raw)[i] ? 1.f : 0.f;
        else if (mode == 1) v = ((const unsigned char*)raw)[i] ? 1.f : 0.f;
        else                v = (((const float*)raw)[i] != 0.f) ? 1.f : 0.f;
        mf[i] = v;
    }
}

// ---------------- batched SGEMM: C[z] = (A @ Bw[z] + bias[z]) * scale ----------------
// A: [M,K] row-major (shared across batches). Bw: [batch][K,N]. C: [batch][M,N].
// Tiles: 128x128x8, 256 threads, 8x8 micro-tile. M%128==0, N%128==0, K%8==0.
__global__ __launch_bounds__(256) void sgemm128_kernel(
    const float* __restrict__ A, const float* __restrict__ Bw,
    const float* __restrict__ bias, float* __restrict__ C,
    int M, int N, int K, float scale)
{
    __shared__ float As[8][128];
    __shared__ float Bs[8][128];

    const int tid = threadIdx.x;
    const int tx = tid & 15, ty = tid >> 4;
    const size_t z = blockIdx.z;
    Bw   += z * (size_t)K * N;
    bias += z * (size_t)N;
    C    += z * (size_t)M * N;

    const int rowBase = blockIdx.y * 128;
    const int colBase = blockIdx.x * 128;

    const int arow = tid >> 1;           // 0..127
    const int aseg = (tid & 1) * 4;      // 0 or 4
    const int brow = tid >> 5;           // 0..7
    const int bcol = (tid & 31) * 4;     // 0..124

    const float* Aptr = A  + (size_t)(rowBase + arow) * K + aseg;
    const float* Bptr = Bw + (size_t)brow * N + colBase + bcol;

    float acc[8][8];
#pragma unroll
    for (int i = 0; i < 8; i++)
#pragma unroll
        for (int j = 0; j < 8; j++) acc[i][j] = 0.f;

    for (int k0 = 0; k0 < K; k0 += 8) {
        float4 av = *(const float4*)(Aptr + k0);
        float4 bv = *(const float4*)(Bptr + (size_t)k0 * N);
        As[aseg + 0][arow] = av.x;
        As[aseg + 1][arow] = av.y;
        As[aseg + 2][arow] = av.z;
        As[aseg + 3][arow] = av.w;
        *(float4*)&Bs[brow][bcol] = bv;
        __syncthreads();

#pragma unroll
        for (int kk = 0; kk < 8; kk++) {
            float4 a0 = *(const float4*)&As[kk][ty * 8];
            float4 a1 = *(const float4*)&As[kk][ty * 8 + 4];
            float4 b0 = *(const float4*)&Bs[kk][tx * 8];
            float4 b1 = *(const float4*)&Bs[kk][tx * 8 + 4];
            float ar[8] = {a0.x, a0.y, a0.z, a0.w, a1.x, a1.y, a1.z, a1.w};
            float br[8] = {b0.x, b0.y, b0.z, b0.w, b1.x, b1.y, b1.z, b1.w};
#pragma unroll
            for (int i = 0; i < 8; i++)
#pragma unroll
                for (int j = 0; j < 8; j++)
                    acc[i][j] += ar[i] * br[j];
        }
        __syncthreads();
    }

    float4 bi0 = *(const float4*)(bias + colBase + tx * 8);
    float4 bi1 = *(const float4*)(bias + colBase + tx * 8 + 4);
    const float bb[8] = {bi0.x, bi0.y, bi0.z, bi0.w, bi1.x, bi1.y, bi1.z, bi1.w};
#pragma unroll
    for (int i = 0; i < 8; i++) {
        size_t row = (size_t)(rowBase + ty * 8 + i);
        float* cp = C + row * N + colBase + tx * 8;
        float4 r0 = make_float4((acc[i][0] + bb[0]) * scale, (acc[i][1] + bb[1]) * scale,
                                (acc[i][2] + bb[2]) * scale, (acc[i][3] + bb[3]) * scale);
        float4 r1 = make_float4((acc[i][4] + bb[4]) * scale, (acc[i][5] + bb[5]) * scale,
                                (acc[i][6] + bb[6]) * scale, (acc[i][7] + bb[7]) * scale);
        *(float4*)cp       = r0;
        *(float4*)(cp + 4) = r1;
    }
}

// ---------------- flash attention over joint (feats || inps) key blocks ----------------
// Qa used against the 8 feats key tiles, Qb against the inps key tile; joint online
// softmax over all 576 keys with per-batch mask (masked -> replaced by -1e9, matching ref).
// Block: 256 threads (16x16), 64 queries, 4x4 micro-tiles for both 64x64 GEMMs.

#define QS_STR 68   // padded row stride for 64-wide smem tiles

__device__ __forceinline__ void load_tile_nat(float* __restrict__ dst,
                                              const float* __restrict__ src, int tid)
{
    // 64 rows x 64 cols from gmem (row stride DC) into smem (row stride QS_STR)
    for (int i = tid; i < 64 * 16; i += 256) {
        int row = i >> 4;
        int c4  = (i & 15) << 2;
        float4 v = *(const float4*)(src + (size_t)row * DC + c4);
        *(float4*)(dst + row * QS_STR + c4) = v;
    }
}

__global__ __launch_bounds__(256) void attn_kernel(
    const float* __restrict__ Qa, const float* __restrict__ Qb,
    const float* __restrict__ Kf, const float* __restrict__ Ki,
    const float* __restrict__ Vf, const float* __restrict__ Vi,
    const float* __restrict__ maskF, float* __restrict__ Out, int Tq)
{
    extern __shared__ float sm[];
    float* Qs = sm;                       // [64][QS_STR]  natural [q][e]
    float* Ks = sm + 64 * QS_STR;         // [64][QS_STR]  transposed [e][k]
    float* Ps = sm + 2 * 64 * QS_STR;     // [64][QS_STR]  natural [q][k]
    float* Vs = sm + 3 * 64 * QS_STR;     // [64][64]      natural [k][e]

    const int tid = threadIdx.x;
    const int tx = tid & 15, ty = tid >> 4;
    const int qt = blockIdx.x, h = blockIdx.y, b = blockIdx.z;
    const int qBase = qt * 64;

    const float* Qa_p = Qa + ((size_t)b * Tq + qBase) * DC + h * EC;
    const float* Qb_p = Qb + ((size_t)b * Tq + qBase) * DC + h * EC;
    const float* Kf_p = Kf + (size_t)b * T1C * DC + h * EC;
    const float* Ki_p = Ki + (size_t)b * T2C * DC + h * EC;
    const float* Vf_p = Vf + (size_t)b * T1C * DC + h * EC;
    const float* Vi_p = Vi + (size_t)b * T2C * DC + h * EC;
    const float* mrow = maskF + b * TKC;

    float O[4][4];
    float m_i[4], l_i[4];
#pragma unroll
    for (int i = 0; i < 4; i++) {
        m_i[i] = -CUDART_INF_F;
        l_i[i] = 0.f;
#pragma unroll
        for (int j = 0; j < 4; j++) O[i][j] = 0.f;
    }

    load_tile_nat(Qs, Qa_p, tid);

    const int nTiles = 9;  // 8 feats tiles + 1 inps tile
    for (int t = 0; t < nTiles; t++) {
        const float* Kp;
        const float* Vp;
        int keyBase;
        if (t < 8) { Kp = Kf_p + (size_t)t * 64 * DC; Vp = Vf_p + (size_t)t * 64 * DC; keyBase = t * 64; }
        else       { Kp = Ki_p;                       Vp = Vi_p;                       keyBase = T1C; }

        __syncthreads();   // everyone done with previous Ks/Vs/Ps (and Qs on switch)
        if (t == 8) load_tile_nat(Qs, Qb_p, tid);   // swap to second query matrix

        // K transposed ([e][k]), V natural ([k][e])
        for (int i = tid; i < 64 * 16; i += 256) {
            int row = i >> 4;
            int c4  = (i & 15) << 2;
            float4 kv = *(const float4*)(Kp + (size_t)row * DC + c4);
            Ks[(c4 + 0) * QS_STR + row] = kv.x;
            Ks[(c4 + 1) * QS_STR + row] = kv.y;
            Ks[(c4 + 2) * QS_STR + row] = kv.z;
            Ks[(c4 + 3) * QS_STR + row] = kv.w;
            float4 vv = *(const float4*)(Vp + (size_t)row * DC + c4);
            *(float4*)&Vs[row * 64 + c4] = vv;
        }
        __syncthreads();

        // S = Q @ K^T  (64x64, 4x4 per thread)
        float s[4][4];
#pragma unroll
        for (int i = 0; i < 4; i++)
#pragma unroll
            for (int j = 0; j < 4; j++) s[i][j] = 0.f;

#pragma unroll 16
        for (int kk = 0; kk < 64; kk++) {
            float qr[4];
#pragma unroll
            for (int i = 0; i < 4; i++) qr[i] = Qs[(ty * 4 + i) * QS_STR + kk];
            float4 kr = *(const float4*)&Ks[kk * QS_STR + tx * 4];
            float ka[4] = {kr.x, kr.y, kr.z, kr.w};
#pragma unroll
            for (int i = 0; i < 4; i++)
#pragma unroll
                for (int j = 0; j < 4; j++) s[i][j] += qr[i] * ka[j];
        }

        // mask: replace (not add) with -1e9, exactly like the reference
        float mk[4];
#pragma unroll
        for (int j = 0; j < 4; j++) mk[j] = mrow[keyBase + tx * 4 + j];
#pragma unroll
        for (int i = 0; i < 4; i++)
#pragma unroll
            for (int j = 0; j < 4; j++)
                if (mk[j] != 0.f) s[i][j] = -1e9f;

        // online softmax update (row stats reduced across the 16 tx lanes)
#pragma unroll
        for (int i = 0; i < 4; i++) {
            float tm = fmaxf(fmaxf(s[i][0], s[i][1]), fmaxf(s[i][2], s[i][3]));
#pragma unroll
            for (int off = 8; off >= 1; off >>= 1)
                tm = fmaxf(tm, __shfl_xor_sync(0xffffffffu, tm, off));
            float mn = fmaxf(m_i[i], tm);
            float sc = __expf(m_i[i] - mn);
            m_i[i] = mn;
            float rs = 0.f;
#pragma unroll
            for (int j = 0; j < 4; j++) {
                s[i][j] = __expf(s[i][j] - mn);
                rs += s[i][j];
            }
#pragma unroll
            for (int off = 8; off >= 1; off >>= 1)
                rs += __shfl_xor_sync(0xffffffffu, rs, off);
            l_i[i] = l_i[i] * sc + rs;
#pragma unroll
            for (int j = 0; j < 4; j++) O[i][j] *= sc;
        }

        // store P (natural [q][k])
#pragma unroll
        for (int i = 0; i < 4; i++)
            *(float4*)&Ps[(ty * 4 + i) * QS_STR + tx * 4] =
                make_float4(s[i][0], s[i][1], s[i][2], s[i][3]);
        __syncthreads();

        // O += P @ V
#pragma unroll 16
        for (int kk = 0; kk < 64; kk++) {
            float pr[4];
#pragma unroll
            for (int i = 0; i < 4; i++) pr[i] = Ps[(ty * 4 + i) * QS_STR + kk];
            float4 vr = *(const float4*)&Vs[kk * 64 + tx * 4];
            float va[4] = {vr.x, vr.y, vr.z, vr.w};
#pragma unroll
            for (int i = 0; i < 4; i++)
#pragma unroll
                for (int j = 0; j < 4; j++) O[i][j] += pr[i] * va[j];
        }
    }

    // epilogue: normalize and write [B][Tq][D] with head offset
#pragma unroll
    for (int i = 0; i < 4; i++) {
        float inv = 1.f / l_i[i];
        int row = qBase + ty * 4 + i;
        float4 o = make_float4(O[i][0] * inv, O[i][1] * inv, O[i][2] * inv, O[i][3] * inv);
        *(float4*)(Out + ((size_t)b * Tq + row) * DC + h * EC + tx * 4) = o;
    }
}

// ---------------- launch ----------------
extern "C" void kernel_launch(void* const* d_in, const int* in_sizes, int n_in,
                              void* d_out, int out_size)
{
    const float* feats = (const float*)d_in[0];
    const float* inps  = (const float*)d_in[1];
    const void*  amask = d_in[2];
    const float* W_f   = (const float*)d_in[3];
    const float* b_f   = (const float*)d_in[4];
    const float* W_i   = (const float*)d_in[5];
    const float* b_i   = (const float*)d_in[6];
    const float* Wu_v  = (const float*)d_in[7];
    const float* bu_v  = (const float*)d_in[8];
    const float* Wu_l  = (const float*)d_in[9];
    const float* bu_l  = (const float*)d_in[10];
    float* out = (float*)d_out;

    float *projF, *projI, *attV, *attL, *maskF;
    cudaGetSymbolAddress((void**)&projF, g_projF);
    cudaGetSymbolAddress((void**)&projI, g_projI);
    cudaGetSymbolAddress((void**)&attV,  g_attV);
    cudaGetSymbolAddress((void**)&attL,  g_attL);
    cudaGetSymbolAddress((void**)&maskF, g_maskF);

    const size_t SF = (size_t)BB * T1C * DC;   // per-projection stride, feats stack
    const size_t SI = (size_t)BB * T2C * DC;   // per-projection stride, inps stack

    const int attnSmem = (3 * 64 * QS_STR + 64 * 64) * (int)sizeof(float);  // 68608 B
    cudaFuncSetAttribute(attn_kernel, cudaFuncAttributeMaxDynamicSharedMemorySize, attnSmem);

    // 1) mask materialization (dtype-robust)
    mask_prep_kernel<<<1, 256>>>((const unsigned*)amask, maskF);

    // 2) projections: [6] batched GEMMs, bias + E^-0.25 scale fused
    sgemm128_kernel<<<dim3(DC / 128, (BB * T1C) / 128, 6), 256>>>(
        feats, W_f, b_f, projF, BB * T1C, DC, DC, SCALE_P);
    sgemm128_kernel<<<dim3(DC / 128, (BB * T2C) / 128, 6), 256>>>(
        inps, W_i, b_i, projI, BB * T2C, DC, DC, SCALE_P);

    // feats stack order:  [k_vv, q_vv, v_vv, q_lv, k_vl, v_vl]
    // inps  stack order:  [k_lv, v_lv, q_vl, q_ll, k_ll, v_ll]

    // 3) visual stream: Qa=q_vv (feats keys), Qb=q_lv (inps keys)
    attn_kernel<<<dim3(T1C / 64, HC, BB), 256, attnSmem>>>(
        projF + 1 * SF, projF + 3 * SF,
        projF + 0 * SF, projI + 0 * SI,
        projF + 2 * SF, projI + 1 * SI,
        maskF, attV, T1C);

    //    language stream: Qa=q_vl (feats keys), Qb=q_ll (inps keys)
    attn_kernel<<<dim3(T2C / 64, HC, BB), 256, attnSmem>>>(
        projI + 2 * SI, projI + 3 * SI,
        projF + 4 * SF, projI + 4 * SI,
        projF + 5 * SF, projI + 5 * SI,
        maskF, attL, T2C);

    // 4) output projections directly into d_out: [out_v | out_l]
    sgemm128_kernel<<<dim3(DC / 128, (BB * T1C) / 128, 1), 256>>>(
        attV, Wu_v, bu_v, out, BB * T1C, DC, DC, 1.0f);
    sgemm128_kernel<<<dim3(DC / 128, (BB * T2C) / 128, 1), 256>>>(
        attL, Wu_l, bu_l, out + SF, BB * T2C, DC, DC, 1.0f);
}

// round 3
// speedup vs baseline: 1.5173x; 1.5173x over previous
#include <cuda_runtime.h>
#include <cuda_bf16.h>
#include <math_constants.h>

// Problem constants
#define BB   16
#define T1C  512
#define T2C  64
#define DC   768
#define HC   12
#define EC   64
#define TKC  576            // T1 + T2
#define SCALE_P 0.3535533905932738f   // 64^-0.25

// ---------------- scratch (device globals; no allocation allowed) ----------------
__device__ float g_projF[6ULL * BB * T1C * DC];   // [6][B][T1][D]
__device__ float g_projI[6ULL * BB * T2C * DC];   // [6][B][T2][D]
__device__ float g_attV [(size_t)BB * T1C * DC];  // [B][T1][D]
__device__ float g_attL [(size_t)BB * T2C * DC];  // [B][T2][D]
__device__ float g_maskF[BB * TKC];               // 1.0 = masked (-> -1e9), 0.0 = keep

// ---------------- mask dtype detection + materialization ----------------
__global__ void mask_prep_kernel(const unsigned* __restrict__ raw, float* __restrict__ mf)
{
    __shared__ int flags[2];   // [0]=notInt32, [1]=notU8
    int tid = threadIdx.x;
    if (tid < 2) flags[tid] = 0;
    __syncthreads();

    int notInt = 0, notU8 = 0;
    const int nWords = (BB * TKC) / 4;
    for (int i = tid; i < nWords; i += blockDim.x) {
        unsigned w = raw[i];
        if (w > 1u) notInt = 1;
        if (w & 0xFEFEFEFEu) notU8 = 1;
    }
    if (notInt) atomicOr(&flags[0], 1);
    if (notU8)  atomicOr(&flags[1], 1);
    __syncthreads();

    int mode;                 // 0 = int32, 1 = uint8, 2 = float32
    if (!flags[0]) mode = 0;
    else if (!flags[1]) mode = 1;
    else mode = 2;

    for (int i = tid; i < BB * TKC; i += blockDim.x) {
        float v;
        if (mode == 0)      v = ((const int*)raw)[i] ? 1.f : 0.f;
        else if (mode == 1) v = ((const unsigned char*)raw)[i] ? 1.f : 0.f;
        else                v = (((const float*)raw)[i] != 0.f) ? 1.f : 0.f;
        mf[i] = v;
    }
}

// ---------------- tf32 tensor-core GEMM ----------------
// C[z] = (A @ Bw[z] + bias[z]) * scale
// A: [M,K] row-major (shared across batch). Bw: [z][K,N]. C: [z][M,N].
// Tiles: 128x128x32, 256 threads (8 warps), warp tile 64x32 via mma.m16n8k8.tf32.
// fp32 -> tf32 conversion (cvt.rna) applied once at smem store.

__device__ __forceinline__ unsigned f2tf32(float x)
{
    unsigned u;
    asm("cvt.rna.tf32.f32 %0, %1;" : "=r"(u) : "f"(x));
    return u;
}

#define AS_STR 36   // 32 + 4 pad: (4*row + k) % 32 distinct across a warp's frag loads

__global__ __launch_bounds__(256) void tf32gemm_kernel(
    const float* __restrict__ A, const float* __restrict__ Bw,
    const float* __restrict__ bias, float* __restrict__ C,
    int M, int N, int K, float scale)
{
    __shared__ unsigned As[128][AS_STR];   // [row][k]   (tf32 bits)
    __shared__ unsigned Bs[128][AS_STR];   // [col][k]   (tf32 bits, B transposed)

    const int tid  = threadIdx.x;
    const int wid  = tid >> 5;
    const int lane = tid & 31;
    const int g    = lane >> 2;      // 0..7
    const int tg   = lane & 3;       // 0..3
    const int warpM = (wid & 1) * 64;
    const int warpN = (wid >> 1) * 32;

    const size_t z = blockIdx.z;
    Bw   += z * (size_t)K * N;
    bias += z * (size_t)N;
    C    += z * (size_t)M * N;

    const int rowBase = blockIdx.y * 128;
    const int colBase = blockIdx.x * 128;

    // gmem load mapping
    const int ar = tid >> 3;             // 0..31  (A row within pass)
    const int ac = (tid & 7) << 2;       // 0..28  (A k, float4)
    const int br = tid >> 5;             // 0..7   (B k-row within pass)
    const int bc = (tid & 31) << 2;      // 0..124 (B n, float4)

    const float* Ap = A  + (size_t)(rowBase + ar) * K + ac;
    const float* Bp = Bw + (size_t)br * N + colBase + bc;

    float acc[4][4][4];
#pragma unroll
    for (int mt = 0; mt < 4; mt++)
#pragma unroll
        for (int nt = 0; nt < 4; nt++)
#pragma unroll
            for (int r = 0; r < 4; r++) acc[mt][nt][r] = 0.f;

    for (int k0 = 0; k0 < K; k0 += 32) {
        __syncthreads();
#pragma unroll
        for (int p = 0; p < 4; p++) {
            float4 av = *(const float4*)(Ap + k0 + (size_t)p * 32 * K);
            unsigned* d = &As[ar + p * 32][ac];
            d[0] = f2tf32(av.x); d[1] = f2tf32(av.y);
            d[2] = f2tf32(av.z); d[3] = f2tf32(av.w);
        }
#pragma unroll
        for (int p = 0; p < 4; p++) {
            float4 bv = *(const float4*)(Bp + (size_t)(k0 + p * 8) * N);
            int kr = br + p * 8;
            Bs[bc + 0][kr] = f2tf32(bv.x);
            Bs[bc + 1][kr] = f2tf32(bv.y);
            Bs[bc + 2][kr] = f2tf32(bv.z);
            Bs[bc + 3][kr] = f2tf32(bv.w);
        }
        __syncthreads();

#pragma unroll
        for (int ks = 0; ks < 32; ks += 8) {
            unsigned a[4][4], b[4][2];
#pragma unroll
            for (int mt = 0; mt < 4; mt++) {
                int r0 = warpM + mt * 16 + g;
                a[mt][0] = As[r0    ][ks + tg];
                a[mt][1] = As[r0 + 8][ks + tg];
                a[mt][2] = As[r0    ][ks + tg + 4];
                a[mt][3] = As[r0 + 8][ks + tg + 4];
            }
#pragma unroll
            for (int nt = 0; nt < 4; nt++) {
                int c0 = warpN + nt * 8 + g;
                b[nt][0] = Bs[c0][ks + tg];
                b[nt][1] = Bs[c0][ks + tg + 4];
            }
#pragma unroll
            for (int mt = 0; mt < 4; mt++)
#pragma unroll
                for (int nt = 0; nt < 4; nt++) {
                    asm volatile(
                        "mma.sync.aligned.m16n8k8.row.col.f32.tf32.tf32.f32 "
                        "{%0,%1,%2,%3}, {%4,%5,%6,%7}, {%8,%9}, {%0,%1,%2,%3};\n"
                        : "+f"(acc[mt][nt][0]), "+f"(acc[mt][nt][1]),
                          "+f"(acc[mt][nt][2]), "+f"(acc[mt][nt][3])
                        : "r"(a[mt][0]), "r"(a[mt][1]), "r"(a[mt][2]), "r"(a[mt][3]),
                          "r"(b[nt][0]), "r"(b[nt][1]));
                }
        }
    }

    // epilogue: bias + scale, float2 stores
#pragma unroll
    for (int mt = 0; mt < 4; mt++) {
        int row0 = rowBase + warpM + mt * 16 + g;
#pragma unroll
        for (int nt = 0; nt < 4; nt++) {
            int col = colBase + warpN + nt * 8 + 2 * tg;
            float b0 = bias[col], b1 = bias[col + 1];
            float2 r0 = make_float2((acc[mt][nt][0] + b0) * scale,
                                    (acc[mt][nt][1] + b1) * scale);
            float2 r1 = make_float2((acc[mt][nt][2] + b0) * scale,
                                    (acc[mt][nt][3] + b1) * scale);
            *(float2*)(C + (size_t)row0 * N + col)       = r0;
            *(float2*)(C + (size_t)(row0 + 8) * N + col) = r1;
        }
    }
}

// ---------------- flash attention over joint (feats || inps) key blocks ----------------
#define QS_STR 68   // padded row stride for 64-wide smem tiles

__device__ __forceinline__ void load_tile_nat(float* __restrict__ dst,
                                              const float* __restrict__ src, int tid)
{
    for (int i = tid; i < 64 * 16; i += 256) {
        int row = i >> 4;
        int c4  = (i & 15) << 2;
        float4 v = *(const float4*)(src + (size_t)row * DC + c4);
        *(float4*)(dst + row * QS_STR + c4) = v;
    }
}

__global__ __launch_bounds__(256) void attn_kernel(
    const float* __restrict__ Qa, const float* __restrict__ Qb,
    const float* __restrict__ Kf, const float* __restrict__ Ki,
    const float* __restrict__ Vf, const float* __restrict__ Vi,
    const float* __restrict__ maskF, float* __restrict__ Out, int Tq)
{
    extern __shared__ float sm[];
    float* Qs = sm;                       // [64][QS_STR]  natural [q][e]
    float* Ks = sm + 64 * QS_STR;         // [64][QS_STR]  transposed [e][k]
    float* Ps = sm + 2 * 64 * QS_STR;     // [64][QS_STR]  natural [q][k]
    float* Vs = sm + 3 * 64 * QS_STR;     // [64][64]      natural [k][e]

    const int tid = threadIdx.x;
    const int tx = tid & 15, ty = tid >> 4;
    const int qt = blockIdx.x, h = blockIdx.y, b = blockIdx.z;
    const int qBase = qt * 64;

    const float* Qa_p = Qa + ((size_t)b * Tq + qBase) * DC + h * EC;
    const float* Qb_p = Qb + ((size_t)b * Tq + qBase) * DC + h * EC;
    const float* Kf_p = Kf + (size_t)b * T1C * DC + h * EC;
    const float* Ki_p = Ki + (size_t)b * T2C * DC + h * EC;
    const float* Vf_p = Vf + (size_t)b * T1C * DC + h * EC;
    const float* Vi_p = Vi + (size_t)b * T2C * DC + h * EC;
    const float* mrow = maskF + b * TKC;

    float O[4][4];
    float m_i[4], l_i[4];
#pragma unroll
    for (int i = 0; i < 4; i++) {
        m_i[i] = -CUDART_INF_F;
        l_i[i] = 0.f;
#pragma unroll
        for (int j = 0; j < 4; j++) O[i][j] = 0.f;
    }

    load_tile_nat(Qs, Qa_p, tid);

    const int nTiles = 9;
    for (int t = 0; t < nTiles; t++) {
        const float* Kp;
        const float* Vp;
        int keyBase;
        if (t < 8) { Kp = Kf_p + (size_t)t * 64 * DC; Vp = Vf_p + (size_t)t * 64 * DC; keyBase = t * 64; }
        else       { Kp = Ki_p;                       Vp = Vi_p;                       keyBase = T1C; }

        __syncthreads();
        if (t == 8) load_tile_nat(Qs, Qb_p, tid);

        for (int i = tid; i < 64 * 16; i += 256) {
            int row = i >> 4;
            int c4  = (i & 15) << 2;
            float4 kv = *(const float4*)(Kp + (size_t)row * DC + c4);
            Ks[(c4 + 0) * QS_STR + row] = kv.x;
            Ks[(c4 + 1) * QS_STR + row] = kv.y;
            Ks[(c4 + 2) * QS_STR + row] = kv.z;
            Ks[(c4 + 3) * QS_STR + row] = kv.w;
            float4 vv = *(const float4*)(Vp + (size_t)row * DC + c4);
            *(float4*)&Vs[row * 64 + c4] = vv;
        }
        __syncthreads();

        float s[4][4];
#pragma unroll
        for (int i = 0; i < 4; i++)
#pragma unroll
            for (int j = 0; j < 4; j++) s[i][j] = 0.f;

#pragma unroll 16
        for (int kk = 0; kk < 64; kk++) {
            float qr[4];
#pragma unroll
            for (int i = 0; i < 4; i++) qr[i] = Qs[(ty * 4 + i) * QS_STR + kk];
            float4 kr = *(const float4*)&Ks[kk * QS_STR + tx * 4];
            float ka[4] = {kr.x, kr.y, kr.z, kr.w};
#pragma unroll
            for (int i = 0; i < 4; i++)
#pragma unroll
                for (int j = 0; j < 4; j++) s[i][j] += qr[i] * ka[j];
        }

        float mk[4];
#pragma unroll
        for (int j = 0; j < 4; j++) mk[j] = mrow[keyBase + tx * 4 + j];
#pragma unroll
        for (int i = 0; i < 4; i++)
#pragma unroll
            for (int j = 0; j < 4; j++)
                if (mk[j] != 0.f) s[i][j] = -1e9f;

#pragma unroll
        for (int i = 0; i < 4; i++) {
            float tm = fmaxf(fmaxf(s[i][0], s[i][1]), fmaxf(s[i][2], s[i][3]));
#pragma unroll
            for (int off = 8; off >= 1; off >>= 1)
                tm = fmaxf(tm, __shfl_xor_sync(0xffffffffu, tm, off));
            float mn = fmaxf(m_i[i], tm);
            float sc = __expf(m_i[i] - mn);
            m_i[i] = mn;
            float rs = 0.f;
#pragma unroll
            for (int j = 0; j < 4; j++) {
                s[i][j] = __expf(s[i][j] - mn);
                rs += s[i][j];
            }
#pragma unroll
            for (int off = 8; off >= 1; off >>= 1)
                rs += __shfl_xor_sync(0xffffffffu, rs, off);
            l_i[i] = l_i[i] * sc + rs;
#pragma unroll
            for (int j = 0; j < 4; j++) O[i][j] *= sc;
        }

#pragma unroll
        for (int i = 0; i < 4; i++)
            *(float4*)&Ps[(ty * 4 + i) * QS_STR + tx * 4] =
                make_float4(s[i][0], s[i][1], s[i][2], s[i][3]);
        __syncthreads();

#pragma unroll 16
        for (int kk = 0; kk < 64; kk++) {
            float pr[4];
#pragma unroll
            for (int i = 0; i < 4; i++) pr[i] = Ps[(ty * 4 + i) * QS_STR + kk];
            float4 vr = *(const float4*)&Vs[kk * 64 + tx * 4];
            float va[4] = {vr.x, vr.y, vr.z, vr.w};
#pragma unroll
            for (int i = 0; i < 4; i++)
#pragma unroll
                for (int j = 0; j < 4; j++) O[i][j] += pr[i] * va[j];
        }
    }

#pragma unroll
    for (int i = 0; i < 4; i++) {
        float inv = 1.f / l_i[i];
        int row = qBase + ty * 4 + i;
        float4 o = make_float4(O[i][0] * inv, O[i][1] * inv, O[i][2] * inv, O[i][3] * inv);
        *(float4*)(Out + ((size_t)b * Tq + row) * DC + h * EC + tx * 4) = o;
    }
}

// ---------------- launch ----------------
extern "C" void kernel_launch(void* const* d_in, const int* in_sizes, int n_in,
                              void* d_out, int out_size)
{
    const float* feats = (const float*)d_in[0];
    const float* inps  = (const float*)d_in[1];
    const void*  amask = d_in[2];
    const float* W_f   = (const float*)d_in[3];
    const float* b_f   = (const float*)d_in[4];
    const float* W_i   = (const float*)d_in[5];
    const float* b_i   = (const float*)d_in[6];
    const float* Wu_v  = (const float*)d_in[7];
    const float* bu_v  = (const float*)d_in[8];
    const float* Wu_l  = (const float*)d_in[9];
    const float* bu_l  = (const float*)d_in[10];
    float* out = (float*)d_out;

    float *projF, *projI, *attV, *attL, *maskF;
    cudaGetSymbolAddress((void**)&projF, g_projF);
    cudaGetSymbolAddress((void**)&projI, g_projI);
    cudaGetSymbolAddress((void**)&attV,  g_attV);
    cudaGetSymbolAddress((void**)&attL,  g_attL);
    cudaGetSymbolAddress((void**)&maskF, g_maskF);

    const size_t SF = (size_t)BB * T1C * DC;
    const size_t SI = (size_t)BB * T2C * DC;

    const int attnSmem = (3 * 64 * QS_STR + 64 * 64) * (int)sizeof(float);
    cudaFuncSetAttribute(attn_kernel, cudaFuncAttributeMaxDynamicSharedMemorySize, attnSmem);

    // 1) mask materialization
    mask_prep_kernel<<<1, 256>>>((const unsigned*)amask, maskF);

    // 2) projections (tf32 tensor cores), bias + E^-0.25 fused
    tf32gemm_kernel<<<dim3(DC / 128, (BB * T1C) / 128, 6), 256>>>(
        feats, W_f, b_f, projF, BB * T1C, DC, DC, SCALE_P);
    tf32gemm_kernel<<<dim3(DC / 128, (BB * T2C) / 128, 6), 256>>>(
        inps, W_i, b_i, projI, BB * T2C, DC, DC, SCALE_P);

    // feats stack: [k_vv, q_vv, v_vv, q_lv, k_vl, v_vl]
    // inps  stack: [k_lv, v_lv, q_vl, q_ll, k_ll, v_ll]

    // 3) attention, both streams
    attn_kernel<<<dim3(T1C / 64, HC, BB), 256, attnSmem>>>(
        projF + 1 * SF, projF + 3 * SF,
        projF + 0 * SF, projI + 0 * SI,
        projF + 2 * SF, projI + 1 * SI,
        maskF, attV, T1C);

    attn_kernel<<<dim3(T2C / 64, HC, BB), 256, attnSmem>>>(
        projI + 2 * SI, projI + 3 * SI,
        projF + 4 * SF, projI + 4 * SI,
        projF + 5 * SF, projI + 5 * SI,
        maskF, attL, T2C);

    // 4) output projections into d_out: [out_v | out_l]
    tf32gemm_kernel<<<dim3(DC / 128, (BB * T1C) / 128, 1), 256>>>(
        attV, Wu_v, bu_v, out, BB * T1C, DC, DC, 1.0f);
    tf32gemm_kernel<<<dim3(DC / 128, (BB * T2C) / 128, 1), 256>>>(
        attL, Wu_l, bu_l, out + SF, BB * T2C, DC, DC, 1.0f);
}

// round 4
// speedup vs baseline: 2.4229x; 1.5969x over previous
#include <cuda_runtime.h>
#include <cuda_bf16.h>
#include <math_constants.h>

// Problem constants
#define BB   16
#define T1C  512
#define T2C  64
#define DC   768
#define HC   12
#define EC   64
#define TKC  576
#define SCALE_P 0.3535533905932738f   // 64^-0.25

// ---------------- scratch (device globals) ----------------
__device__ float    g_projF[6ULL * BB * T1C * DC];   // tf32-bit floats
__device__ float    g_projI[6ULL * BB * T2C * DC];   // tf32-bit floats
__device__ float    g_attV [(size_t)BB * T1C * DC];  // tf32-bit floats
__device__ float    g_attL [(size_t)BB * T2C * DC];  // tf32-bit floats
__device__ float    g_maskF[BB * TKC];
__device__ unsigned g_featsT[(size_t)BB * T1C * DC];
__device__ unsigned g_inpsT [(size_t)BB * T2C * DC];
__device__ unsigned g_WfT[6ULL * DC * DC];
__device__ unsigned g_WiT[6ULL * DC * DC];
__device__ unsigned g_WuvT[(size_t)DC * DC];
__device__ unsigned g_WulT[(size_t)DC * DC];

__device__ __forceinline__ unsigned f2tf32(float x)
{
    unsigned u;
    asm("cvt.rna.tf32.f32 %0, %1;" : "=r"(u) : "f"(x));
    return u;
}

#define MMA_TF32(d, a0, a1, a2, a3, b0, b1)                                   \
    asm volatile("mma.sync.aligned.m16n8k8.row.col.f32.tf32.tf32.f32 "        \
                 "{%0,%1,%2,%3}, {%4,%5,%6,%7}, {%8,%9}, {%0,%1,%2,%3};\n"    \
                 : "+f"(d[0]), "+f"(d[1]), "+f"(d[2]), "+f"(d[3])             \
                 : "r"(a0), "r"(a1), "r"(a2), "r"(a3), "r"(b0), "r"(b1))

__device__ __forceinline__ void cp16(void* dst, const void* src)
{
    unsigned sa = (unsigned)__cvta_generic_to_shared(dst);
    asm volatile("cp.async.ca.shared.global [%0], [%1], 16;" :: "r"(sa), "l"(src));
}
#define CP_COMMIT() asm volatile("cp.async.commit_group;")
template <int N>
__device__ __forceinline__ void cp_wait() { asm volatile("cp.async.wait_group %0;" :: "n"(N)); }

// ---------------- mask dtype detection + materialization ----------------
__global__ void mask_prep_kernel(const unsigned* __restrict__ raw, float* __restrict__ mf)
{
    __shared__ int flags[2];
    int tid = threadIdx.x;
    if (tid < 2) flags[tid] = 0;
    __syncthreads();

    int notInt = 0, notU8 = 0;
    const int nWords = (BB * TKC) / 4;
    for (int i = tid; i < nWords; i += blockDim.x) {
        unsigned w = raw[i];
        if (w > 1u) notInt = 1;
        if (w & 0xFEFEFEFEu) notU8 = 1;
    }
    if (notInt) atomicOr(&flags[0], 1);
    if (notU8)  atomicOr(&flags[1], 1);
    __syncthreads();

    int mode;
    if (!flags[0]) mode = 0;
    else if (!flags[1]) mode = 1;
    else mode = 2;

    for (int i = tid; i < BB * TKC; i += blockDim.x) {
        float v;
        if (mode == 0)      v = ((const int*)raw)[i] ? 1.f : 0.f;
        else if (mode == 1) v = ((const unsigned char*)raw)[i] ? 1.f : 0.f;
        else                v = (((const float*)raw)[i] != 0.f) ? 1.f : 0.f;
        mf[i] = v;
    }
}

// ---------------- fp32 -> tf32 bit pre-conversion ----------------
__global__ void cvt_tf32_kernel(const float4* __restrict__ src, uint4* __restrict__ dst, int n4)
{
    int i = blockIdx.x * blockDim.x + threadIdx.x;
    int stride = gridDim.x * blockDim.x;
    for (; i < n4; i += stride) {
        float4 v = src[i];
        uint4 u;
        u.x = f2tf32(v.x); u.y = f2tf32(v.y); u.z = f2tf32(v.z); u.w = f2tf32(v.w);
        dst[i] = u;
    }
}

// ---------------- pipelined tf32 GEMM ----------------
// C[z] = (A @ Bw[z] + bias[z]) * scale;  A,Bw pre-converted tf32 bits.
// 128x128x32 tiles, 256 threads, 2-stage cp.async pipeline.
// As: [2][128][36] ([row][k], pad 36 -> frag banks 4g+tg conflict-free)
// Bs: [2][32][136] ([k][n],  pad 136 -> frag banks 8tg+g conflict-free)
#define GA_STR 36
#define GB_STR 136
#define GSM_A (128 * GA_STR)
#define GSM_B (32 * GB_STR)

__global__ __launch_bounds__(256, 2) void tf32gemm2_kernel(
    const unsigned* __restrict__ A, const unsigned* __restrict__ Bw,
    const float* __restrict__ bias, float* __restrict__ C,
    int M, int N, int K, float scale, int outTf32)
{
    extern __shared__ unsigned sh[];
    unsigned* As = sh;                 // 2 stages
    unsigned* Bs = sh + 2 * GSM_A;

    const int tid  = threadIdx.x;
    const int wid  = tid >> 5;
    const int lane = tid & 31;
    const int g    = lane >> 2;
    const int tg   = lane & 3;
    const int warpM = (wid & 1) * 64;
    const int warpN = (wid >> 1) * 32;

    const size_t z = blockIdx.z;
    Bw   += z * (size_t)K * N;
    bias += z * (size_t)N;
    C    += z * (size_t)M * N;

    const int rowBase = blockIdx.y * 128;
    const int colBase = blockIdx.x * 128;

    // cp.async mappings
    const int arow = tid >> 1,  acol = (tid & 1) * 16;   // A: 128 rows x 2 segs
    const int brow = tid >> 3,  bcol = (tid & 7) * 16;   // B: 32 k-rows x 8 segs

    const unsigned* Ag = A  + (size_t)(rowBase + arow) * K + acol;
    const unsigned* Bg = Bw + (size_t)brow * N + colBase + bcol;

    unsigned* AdBase = As + arow * GA_STR + acol;
    unsigned* BdBase = Bs + brow * GB_STR + bcol;

    float acc[4][4][4];
#pragma unroll
    for (int mt = 0; mt < 4; mt++)
#pragma unroll
        for (int nt = 0; nt < 4; nt++)
#pragma unroll
            for (int r = 0; r < 4; r++) acc[mt][nt][r] = 0.f;

    const int NC = K / 32;

    // prologue: stage 0
    {
#pragma unroll
        for (int j = 0; j < 4; j++) cp16(AdBase + j * 4, Ag + j * 4);
#pragma unroll
        for (int j = 0; j < 4; j++) cp16(BdBase + j * 4, Bg + j * 4);
        CP_COMMIT();
    }

    int buf = 0;
    for (int c = 0; c < NC; c++) {
        if (c + 1 < NC) {
            int st = buf ^ 1;
            const unsigned* Asrc = Ag + (c + 1) * 32;
            const unsigned* Bsrc = Bg + (size_t)(c + 1) * 32 * N;
            unsigned* Ad = AdBase + st * GSM_A;
            unsigned* Bd = BdBase + st * GSM_B;
#pragma unroll
            for (int j = 0; j < 4; j++) cp16(Ad + j * 4, Asrc + j * 4);
#pragma unroll
            for (int j = 0; j < 4; j++) cp16(Bd + j * 4, Bsrc + j * 4);
            CP_COMMIT();
            cp_wait<1>();
        } else {
            cp_wait<0>();
        }
        __syncthreads();

        const unsigned* Ab = As + buf * GSM_A;
        const unsigned* Bb = Bs + buf * GSM_B;
#pragma unroll
        for (int ks = 0; ks < 32; ks += 8) {
            unsigned a[4][4];
#pragma unroll
            for (int mt = 0; mt < 4; mt++) {
                int r0 = warpM + mt * 16 + g;
                a[mt][0] = Ab[r0 * GA_STR + ks + tg];
                a[mt][1] = Ab[(r0 + 8) * GA_STR + ks + tg];
                a[mt][2] = Ab[r0 * GA_STR + ks + tg + 4];
                a[mt][3] = Ab[(r0 + 8) * GA_STR + ks + tg + 4];
            }
            unsigned bf[4][2];
#pragma unroll
            for (int nt = 0; nt < 4; nt++) {
                int c0 = warpN + nt * 8 + g;
                bf[nt][0] = Bb[(ks + tg) * GB_STR + c0];
                bf[nt][1] = Bb[(ks + tg + 4) * GB_STR + c0];
            }
#pragma unroll
            for (int mt = 0; mt < 4; mt++)
#pragma unroll
                for (int nt = 0; nt < 4; nt++)
                    MMA_TF32(acc[mt][nt], a[mt][0], a[mt][1], a[mt][2], a[mt][3],
                             bf[nt][0], bf[nt][1]);
        }
        __syncthreads();
        buf ^= 1;
    }

    // epilogue
#pragma unroll
    for (int mt = 0; mt < 4; mt++) {
        int row0 = rowBase + warpM + mt * 16 + g;
#pragma unroll
        for (int nt = 0; nt < 4; nt++) {
            int col = colBase + warpN + nt * 8 + 2 * tg;
            float b0 = bias[col], b1 = bias[col + 1];
            float v0 = (acc[mt][nt][0] + b0) * scale;
            float v1 = (acc[mt][nt][1] + b1) * scale;
            float v2 = (acc[mt][nt][2] + b0) * scale;
            float v3 = (acc[mt][nt][3] + b1) * scale;
            if (outTf32) {
                v0 = __uint_as_float(f2tf32(v0));
                v1 = __uint_as_float(f2tf32(v1));
                v2 = __uint_as_float(f2tf32(v2));
                v3 = __uint_as_float(f2tf32(v3));
            }
            *(float2*)(C + (size_t)row0 * N + col)       = make_float2(v0, v1);
            *(float2*)(C + (size_t)(row0 + 8) * N + col) = make_float2(v2, v3);
        }
    }
}

// ---------------- mma-based flash attention ----------------
// 128 threads / 4 warps; warp owns 16 query rows. Joint softmax over 576 keys
// (8 feats tiles w/ Qa, 1 inps tile w/ Qb). Inputs are tf32-bit floats.
#define APAD 68   // frag banks 4g+tg conflict-free
#define VPAD 72   // frag banks 8tg+g conflict-free

__global__ __launch_bounds__(128) void attn_mma_kernel(
    const float* __restrict__ Qa, const float* __restrict__ Qb,
    const float* __restrict__ Kf, const float* __restrict__ Ki,
    const float* __restrict__ Vf, const float* __restrict__ Vi,
    const float* __restrict__ maskF, float* __restrict__ Out, int Tq)
{
    extern __shared__ unsigned smu[];
    unsigned* Qs = smu;                     // [64][APAD] tf32 [q][d]
    unsigned* Ks = Qs + 64 * APAD;          // [64][APAD] tf32 [key][d]
    unsigned* Vs = Ks + 64 * APAD;          // [64][VPAD] tf32 [key][e]
    unsigned* Ps = Vs + 64 * VPAD;          // [64][APAD] tf32 [q][key]
    float*    Ms = (float*)(Ps + 64 * APAD); // [TKC]

    const int tid  = threadIdx.x;
    const int wid  = tid >> 5;
    const int lane = tid & 31;
    const int g    = lane >> 2;
    const int tg   = lane & 3;
    const int wr   = wid * 16;

    const int qt = blockIdx.x, h = blockIdx.y, b = blockIdx.z;
    const int qBase = qt * 64;

    const float* Qa_p = Qa + ((size_t)b * Tq + qBase) * DC + h * EC;
    const float* Qb_p = Qb + ((size_t)b * Tq + qBase) * DC + h * EC;
    const float* Kf_p = Kf + (size_t)b * T1C * DC + h * EC;
    const float* Ki_p = Ki + (size_t)b * T2C * DC + h * EC;
    const float* Vf_p = Vf + (size_t)b * T1C * DC + h * EC;
    const float* Vi_p = Vi + (size_t)b * T2C * DC + h * EC;

    for (int i = tid; i < TKC; i += 128) Ms[i] = maskF[b * TKC + i];

    // load Qa (bit copy, already tf32)
    for (int i = tid; i < 64 * 16; i += 128) {
        int r = i >> 4, c = (i & 15) << 2;
        uint4 v = *(const uint4*)(Qa_p + (size_t)r * DC + c);
        *(uint4*)&Qs[r * APAD + c] = v;
    }

    float o[8][4];
#pragma unroll
    for (int et = 0; et < 8; et++)
#pragma unroll
        for (int r = 0; r < 4; r++) o[et][r] = 0.f;
    float mx0 = -CUDART_INF_F, mx1 = -CUDART_INF_F, l0 = 0.f, l1 = 0.f;

    for (int t = 0; t < 9; t++) {
        const float *Kp, *Vp;
        int keyBase;
        if (t < 8) { Kp = Kf_p + (size_t)t * 64 * DC; Vp = Vf_p + (size_t)t * 64 * DC; keyBase = t * 64; }
        else       { Kp = Ki_p;                       Vp = Vi_p;                       keyBase = T1C; }

        __syncthreads();   // previous tile's PV done before overwriting Ks/Vs (and Qs)
        if (t == 8) {
            for (int i = tid; i < 64 * 16; i += 128) {
                int r = i >> 4, c = (i & 15) << 2;
                uint4 v = *(const uint4*)(Qb_p + (size_t)r * DC + c);
                *(uint4*)&Qs[r * APAD + c] = v;
            }
        }
        for (int i = tid; i < 64 * 16; i += 128) {
            int r = i >> 4, c = (i & 15) << 2;
            uint4 kv = *(const uint4*)(Kp + (size_t)r * DC + c);
            *(uint4*)&Ks[r * APAD + c] = kv;
            uint4 vv = *(const uint4*)(Vp + (size_t)r * DC + c);
            *(uint4*)&Vs[r * VPAD + c] = vv;
        }
        __syncthreads();

        // S = Q @ K^T : warp computes 16x64
        float s[8][4];
#pragma unroll
        for (int nt = 0; nt < 8; nt++)
#pragma unroll
            for (int r = 0; r < 4; r++) s[nt][r] = 0.f;

#pragma unroll
        for (int ks = 0; ks < 64; ks += 8) {
            unsigned a0 = Qs[(wr + g) * APAD + ks + tg];
            unsigned a1 = Qs[(wr + g + 8) * APAD + ks + tg];
            unsigned a2 = Qs[(wr + g) * APAD + ks + tg + 4];
            unsigned a3 = Qs[(wr + g + 8) * APAD + ks + tg + 4];
#pragma unroll
            for (int nt = 0; nt < 8; nt++) {
                unsigned b0 = Ks[(nt * 8 + g) * APAD + ks + tg];
                unsigned b1 = Ks[(nt * 8 + g) * APAD + ks + tg + 4];
                MMA_TF32(s[nt], a0, a1, a2, a3, b0, b1);
            }
        }

        // mask (replace with -1e9) + row max
        float tm0 = -CUDART_INF_F, tm1 = -CUDART_INF_F;
#pragma unroll
        for (int nt = 0; nt < 8; nt++) {
            float mk0 = Ms[keyBase + nt * 8 + 2 * tg];
            float mk1 = Ms[keyBase + nt * 8 + 2 * tg + 1];
            if (mk0 != 0.f) { s[nt][0] = -1e9f; s[nt][2] = -1e9f; }
            if (mk1 != 0.f) { s[nt][1] = -1e9f; s[nt][3] = -1e9f; }
            tm0 = fmaxf(tm0, fmaxf(s[nt][0], s[nt][1]));
            tm1 = fmaxf(tm1, fmaxf(s[nt][2], s[nt][3]));
        }
        tm0 = fmaxf(tm0, __shfl_xor_sync(0xffffffffu, tm0, 1));
        tm0 = fmaxf(tm0, __shfl_xor_sync(0xffffffffu, tm0, 2));
        tm1 = fmaxf(tm1, __shfl_xor_sync(0xffffffffu, tm1, 1));
        tm1 = fmaxf(tm1, __shfl_xor_sync(0xffffffffu, tm1, 2));

        float mn0 = fmaxf(mx0, tm0), mn1 = fmaxf(mx1, tm1);
        float sc0 = __expf(mx0 - mn0), sc1 = __expf(mx1 - mn1);
        mx0 = mn0; mx1 = mn1;

        float rs0 = 0.f, rs1 = 0.f;
#pragma unroll
        for (int nt = 0; nt < 8; nt++) {
            s[nt][0] = __expf(s[nt][0] - mn0); rs0 += s[nt][0];
            s[nt][1] = __expf(s[nt][1] - mn0); rs0 += s[nt][1];
            s[nt][2] = __expf(s[nt][2] - mn1); rs1 += s[nt][2];
            s[nt][3] = __expf(s[nt][3] - mn1); rs1 += s[nt][3];
        }
        rs0 += __shfl_xor_sync(0xffffffffu, rs0, 1);
        rs0 += __shfl_xor_sync(0xffffffffu, rs0, 2);
        rs1 += __shfl_xor_sync(0xffffffffu, rs1, 1);
        rs1 += __shfl_xor_sync(0xffffffffu, rs1, 2);
        l0 = l0 * sc0 + rs0;
        l1 = l1 * sc1 + rs1;
#pragma unroll
        for (int et = 0; et < 8; et++) {
            o[et][0] *= sc0; o[et][1] *= sc0;
            o[et][2] *= sc1; o[et][3] *= sc1;
        }

        // write P (per-warp rows only -> warp-local sync suffices)
#pragma unroll
        for (int nt = 0; nt < 8; nt++) {
            uint2 p0 = make_uint2(f2tf32(s[nt][0]), f2tf32(s[nt][1]));
            uint2 p1 = make_uint2(f2tf32(s[nt][2]), f2tf32(s[nt][3]));
            *(uint2*)&Ps[(wr + g) * APAD + nt * 8 + 2 * tg]     = p0;
            *(uint2*)&Ps[(wr + g + 8) * APAD + nt * 8 + 2 * tg] = p1;
        }
        __syncwarp();

        // O += P @ V
#pragma unroll
        for (int ks = 0; ks < 64; ks += 8) {
            unsigned a0 = Ps[(wr + g) * APAD + ks + tg];
            unsigned a1 = Ps[(wr + g + 8) * APAD + ks + tg];
            unsigned a2 = Ps[(wr + g) * APAD + ks + tg + 4];
            unsigned a3 = Ps[(wr + g + 8) * APAD + ks + tg + 4];
#pragma unroll
            for (int et = 0; et < 8; et++) {
                unsigned b0 = Vs[(ks + tg) * VPAD + et * 8 + g];
                unsigned b1 = Vs[(ks + tg + 4) * VPAD + et * 8 + g];
                MMA_TF32(o[et], a0, a1, a2, a3, b0, b1);
            }
        }
    }

    // epilogue: normalize, write tf32-bit floats (feeds the tf32 out-proj GEMM)
    float inv0 = 1.f / l0, inv1 = 1.f / l1;
    int r0 = qBase + wr + g;
#pragma unroll
    for (int et = 0; et < 8; et++) {
        int col = h * EC + et * 8 + 2 * tg;
        uint2 v0 = make_uint2(f2tf32(o[et][0] * inv0), f2tf32(o[et][1] * inv0));
        uint2 v1 = make_uint2(f2tf32(o[et][2] * inv1), f2tf32(o[et][3] * inv1));
        *(uint2*)(Out + ((size_t)b * Tq + r0) * DC + col)     = v0;
        *(uint2*)(Out + ((size_t)b * Tq + r0 + 8) * DC + col) = v1;
    }
}

// ---------------- launch ----------------
extern "C" void kernel_launch(void* const* d_in, const int* in_sizes, int n_in,
                              void* d_out, int out_size)
{
    const float* feats = (const float*)d_in[0];
    const float* inps  = (const float*)d_in[1];
    const void*  amask = d_in[2];
    const float* W_f   = (const float*)d_in[3];
    const float* b_f   = (const float*)d_in[4];
    const float* W_i   = (const float*)d_in[5];
    const float* b_i   = (const float*)d_in[6];
    const float* Wu_v  = (const float*)d_in[7];
    const float* bu_v  = (const float*)d_in[8];
    const float* Wu_l  = (const float*)d_in[9];
    const float* bu_l  = (const float*)d_in[10];
    float* out = (float*)d_out;

    float *projF, *projI, *attV, *attL, *maskF;
    unsigned *featsT, *inpsT, *WfT, *WiT, *WuvT, *WulT;
    cudaGetSymbolAddress((void**)&projF, g_projF);
    cudaGetSymbolAddress((void**)&projI, g_projI);
    cudaGetSymbolAddress((void**)&attV,  g_attV);
    cudaGetSymbolAddress((void**)&attL,  g_attL);
    cudaGetSymbolAddress((void**)&maskF, g_maskF);
    cudaGetSymbolAddress((void**)&featsT, g_featsT);
    cudaGetSymbolAddress((void**)&inpsT,  g_inpsT);
    cudaGetSymbolAddress((void**)&WfT,  g_WfT);
    cudaGetSymbolAddress((void**)&WiT,  g_WiT);
    cudaGetSymbolAddress((void**)&WuvT, g_WuvT);
    cudaGetSymbolAddress((void**)&WulT, g_WulT);

    const size_t SF = (size_t)BB * T1C * DC;
    const size_t SI = (size_t)BB * T2C * DC;

    const int gemmSmem = (2 * GSM_A + 2 * GSM_B) * (int)sizeof(unsigned);          // 71680
    const int attnSmem = (3 * 64 * APAD + 64 * VPAD + TKC) * (int)sizeof(unsigned); // 72960
    cudaFuncSetAttribute(tf32gemm2_kernel, cudaFuncAttributeMaxDynamicSharedMemorySize, gemmSmem);
    cudaFuncSetAttribute(attn_mma_kernel,  cudaFuncAttributeMaxDynamicSharedMemorySize, attnSmem);

    // 1) mask + tf32 pre-conversion
    mask_prep_kernel<<<1, 256>>>((const unsigned*)amask, maskF);
    cvt_tf32_kernel<<<1024, 256>>>((const float4*)feats, (uint4*)featsT, (int)(SF / 4));
    cvt_tf32_kernel<<<256, 256>>>((const float4*)inps,  (uint4*)inpsT,  (int)(SI / 4));
    cvt_tf32_kernel<<<1024, 256>>>((const float4*)W_f,  (uint4*)WfT,  6 * DC * DC / 4);
    cvt_tf32_kernel<<<1024, 256>>>((const float4*)W_i,  (uint4*)WiT,  6 * DC * DC / 4);
    cvt_tf32_kernel<<<256, 256>>>((const float4*)Wu_v, (uint4*)WuvT, DC * DC / 4);
    cvt_tf32_kernel<<<256, 256>>>((const float4*)Wu_l, (uint4*)WulT, DC * DC / 4);

    // 2) projections (tf32 out), bias + E^-0.25 fused
    tf32gemm2_kernel<<<dim3(DC / 128, (BB * T1C) / 128, 6), 256, gemmSmem>>>(
        featsT, WfT, b_f, projF, BB * T1C, DC, DC, SCALE_P, 1);
    tf32gemm2_kernel<<<dim3(DC / 128, (BB * T2C) / 128, 6), 256, gemmSmem>>>(
        inpsT, WiT, b_i, projI, BB * T2C, DC, DC, SCALE_P, 1);

    // feats stack: [k_vv, q_vv, v_vv, q_lv, k_vl, v_vl]
    // inps  stack: [k_lv, v_lv, q_vl, q_ll, k_ll, v_ll]

    // 3) attention, both streams (outputs tf32-bit floats)
    attn_mma_kernel<<<dim3(T1C / 64, HC, BB), 128, attnSmem>>>(
        projF + 1 * SF, projF + 3 * SF,
        projF + 0 * SF, projI + 0 * SI,
        projF + 2 * SF, projI + 1 * SI,
        maskF, attV, T1C);
    attn_mma_kernel<<<dim3(T2C / 64, HC, BB), 128, attnSmem>>>(
        projI + 2 * SI, projI + 3 * SI,
        projF + 4 * SF, projI + 4 * SI,
        projF + 5 * SF, projI + 5 * SI,
        maskF, attL, T2C);

    // 4) output projections (fp32 out) into d_out: [out_v | out_l]
    tf32gemm2_kernel<<<dim3(DC / 128, (BB * T1C) / 128, 1), 256, gemmSmem>>>(
        (const unsigned*)attV, WuvT, bu_v, out, BB * T1C, DC, DC, 1.0f, 0);
    tf32gemm2_kernel<<<dim3(DC / 128, (BB * T2C) / 128, 1), 256, gemmSmem>>>(
        (const unsigned*)attL, WulT, bu_l, out + SF, BB * T2C, DC, DC, 1.0f, 0);
}

// round 5
// speedup vs baseline: 2.4232x; 1.0001x over previous
#include <cuda_runtime.h>
#include <cuda_bf16.h>
#include <math_constants.h>

// Problem constants
#define BB   16
#define T1C  512
#define T2C  64
#define DC   768
#define HC   12
#define EC   64
#define TKC  576
#define SCALE_P 0.3535533905932738f   // 64^-0.25

// ---------------- scratch (device globals) ----------------
__device__ float    g_projF[6ULL * BB * T1C * DC];   // tf32-bit floats
__device__ float    g_projI[6ULL * BB * T2C * DC];   // tf32-bit floats
__device__ float    g_attV [(size_t)BB * T1C * DC];  // tf32-bit floats
__device__ float    g_attL [(size_t)BB * T2C * DC];  // tf32-bit floats
__device__ float    g_maskF[BB * TKC];
__device__ unsigned g_featsT[(size_t)BB * T1C * DC];
__device__ unsigned g_inpsT [(size_t)BB * T2C * DC];
__device__ unsigned g_WfT[6ULL * DC * DC];
__device__ unsigned g_WiT[6ULL * DC * DC];
__device__ unsigned g_WuvT[(size_t)DC * DC];
__device__ unsigned g_WulT[(size_t)DC * DC];

__device__ __forceinline__ unsigned f2tf32(float x)
{
    unsigned u;
    asm("cvt.rna.tf32.f32 %0, %1;" : "=r"(u) : "f"(x));
    return u;
}

#define MMA_TF32(d, a0, a1, a2, a3, b0, b1)                                   \
    asm volatile("mma.sync.aligned.m16n8k8.row.col.f32.tf32.tf32.f32 "        \
                 "{%0,%1,%2,%3}, {%4,%5,%6,%7}, {%8,%9}, {%0,%1,%2,%3};\n"    \
                 : "+f"(d[0]), "+f"(d[1]), "+f"(d[2]), "+f"(d[3])             \
                 : "r"(a0), "r"(a1), "r"(a2), "r"(a3), "r"(b0), "r"(b1))

__device__ __forceinline__ void cp16(void* dst, const void* src)
{
    unsigned sa = (unsigned)__cvta_generic_to_shared(dst);
    asm volatile("cp.async.ca.shared.global [%0], [%1], 16;" :: "r"(sa), "l"(src));
}
#define CP_COMMIT() asm volatile("cp.async.commit_group;")
template <int N>
__device__ __forceinline__ void cp_wait() { asm volatile("cp.async.wait_group %0;" :: "n"(N)); }

// ---------------- mask dtype detection + materialization ----------------
__global__ void mask_prep_kernel(const unsigned* __restrict__ raw, float* __restrict__ mf)
{
    __shared__ int flags[2];
    int tid = threadIdx.x;
    if (tid < 2) flags[tid] = 0;
    __syncthreads();

    int notInt = 0, notU8 = 0;
    const int nWords = (BB * TKC) / 4;
    for (int i = tid; i < nWords; i += blockDim.x) {
        unsigned w = raw[i];
        if (w > 1u) notInt = 1;
        if (w & 0xFEFEFEFEu) notU8 = 1;
    }
    if (notInt) atomicOr(&flags[0], 1);
    if (notU8)  atomicOr(&flags[1], 1);
    __syncthreads();

    int mode;
    if (!flags[0]) mode = 0;
    else if (!flags[1]) mode = 1;
    else mode = 2;

    for (int i = tid; i < BB * TKC; i += blockDim.x) {
        float v;
        if (mode == 0)      v = ((const int*)raw)[i] ? 1.f : 0.f;
        else if (mode == 1) v = ((const unsigned char*)raw)[i] ? 1.f : 0.f;
        else                v = (((const float*)raw)[i] != 0.f) ? 1.f : 0.f;
        mf[i] = v;
    }
}

// ---------------- fp32 -> tf32 bit pre-conversion ----------------
__global__ void cvt_tf32_kernel(const float4* __restrict__ src, uint4* __restrict__ dst, int n4)
{
    int i = blockIdx.x * blockDim.x + threadIdx.x;
    int stride = gridDim.x * blockDim.x;
    for (; i < n4; i += stride) {
        float4 v = src[i];
        uint4 u;
        u.x = f2tf32(v.x); u.y = f2tf32(v.y); u.z = f2tf32(v.z); u.w = f2tf32(v.w);
        dst[i] = u;
    }
}

// ---------------- pipelined tf32 GEMM ----------------
// C[z] = (A @ Bw[z] + bias[z]) * scale;  A,Bw pre-converted tf32 bits.
// 128x128x32 tiles, 256 threads, 2-stage cp.async pipeline.
// As: [2][128][36] ([row][k], pad 36 -> frag banks 4g+tg conflict-free)
// Bs: [2][32][136] ([k][n],  pad 136 -> frag banks 8tg+g conflict-free)
#define GA_STR 36
#define GB_STR 136
#define GSM_A (128 * GA_STR)
#define GSM_B (32 * GB_STR)

__global__ __launch_bounds__(256, 2) void tf32gemm2_kernel(
    const unsigned* __restrict__ A, const unsigned* __restrict__ Bw,
    const float* __restrict__ bias, float* __restrict__ C,
    int M, int N, int K, float scale, int outTf32)
{
    extern __shared__ unsigned sh[];
    unsigned* As = sh;                 // 2 stages
    unsigned* Bs = sh + 2 * GSM_A;

    const int tid  = threadIdx.x;
    const int wid  = tid >> 5;
    const int lane = tid & 31;
    const int g    = lane >> 2;
    const int tg   = lane & 3;
    const int warpM = (wid & 1) * 64;
    const int warpN = (wid >> 1) * 32;

    const size_t z = blockIdx.z;
    Bw   += z * (size_t)K * N;
    bias += z * (size_t)N;
    C    += z * (size_t)M * N;

    const int rowBase = blockIdx.y * 128;
    const int colBase = blockIdx.x * 128;

    // cp.async mappings
    const int arow = tid >> 1,  acol = (tid & 1) * 16;   // A: 128 rows x 2 segs
    const int brow = tid >> 3,  bcol = (tid & 7) * 16;   // B: 32 k-rows x 8 segs

    const unsigned* Ag = A  + (size_t)(rowBase + arow) * K + acol;
    const unsigned* Bg = Bw + (size_t)brow * N + colBase + bcol;

    unsigned* AdBase = As + arow * GA_STR + acol;
    unsigned* BdBase = Bs + brow * GB_STR + bcol;

    float acc[4][4][4];
#pragma unroll
    for (int mt = 0; mt < 4; mt++)
#pragma unroll
        for (int nt = 0; nt < 4; nt++)
#pragma unroll
            for (int r = 0; r < 4; r++) acc[mt][nt][r] = 0.f;

    const int NC = K / 32;

    // prologue: stage 0
    {
#pragma unroll
        for (int j = 0; j < 4; j++) cp16(AdBase + j * 4, Ag + j * 4);
#pragma unroll
        for (int j = 0; j < 4; j++) cp16(BdBase + j * 4, Bg + j * 4);
        CP_COMMIT();
    }

    int buf = 0;
    for (int c = 0; c < NC; c++) {
        if (c + 1 < NC) {
            int st = buf ^ 1;
            const unsigned* Asrc = Ag + (c + 1) * 32;
            const unsigned* Bsrc = Bg + (size_t)(c + 1) * 32 * N;
            unsigned* Ad = AdBase + st * GSM_A;
            unsigned* Bd = BdBase + st * GSM_B;
#pragma unroll
            for (int j = 0; j < 4; j++) cp16(Ad + j * 4, Asrc + j * 4);
#pragma unroll
            for (int j = 0; j < 4; j++) cp16(Bd + j * 4, Bsrc + j * 4);
            CP_COMMIT();
            cp_wait<1>();
        } else {
            cp_wait<0>();
        }
        __syncthreads();

        const unsigned* Ab = As + buf * GSM_A;
        const unsigned* Bb = Bs + buf * GSM_B;
#pragma unroll
        for (int ks = 0; ks < 32; ks += 8) {
            unsigned a[4][4];
#pragma unroll
            for (int mt = 0; mt < 4; mt++) {
                int r0 = warpM + mt * 16 + g;
                a[mt][0] = Ab[r0 * GA_STR + ks + tg];
                a[mt][1] = Ab[(r0 + 8) * GA_STR + ks + tg];
                a[mt][2] = Ab[r0 * GA_STR + ks + tg + 4];
                a[mt][3] = Ab[(r0 + 8) * GA_STR + ks + tg + 4];
            }
            unsigned bf[4][2];
#pragma unroll
            for (int nt = 0; nt < 4; nt++) {
                int c0 = warpN + nt * 8 + g;
                bf[nt][0] = Bb[(ks + tg) * GB_STR + c0];
                bf[nt][1] = Bb[(ks + tg + 4) * GB_STR + c0];
            }
#pragma unroll
            for (int mt = 0; mt < 4; mt++)
#pragma unroll
                for (int nt = 0; nt < 4; nt++)
                    MMA_TF32(acc[mt][nt], a[mt][0], a[mt][1], a[mt][2], a[mt][3],
                             bf[nt][0], bf[nt][1]);
        }
        __syncthreads();
        buf ^= 1;
    }

    // epilogue
#pragma unroll
    for (int mt = 0; mt < 4; mt++) {
        int row0 = rowBase + warpM + mt * 16 + g;
#pragma unroll
        for (int nt = 0; nt < 4; nt++) {
            int col = colBase + warpN + nt * 8 + 2 * tg;
            float b0 = bias[col], b1 = bias[col + 1];
            float v0 = (acc[mt][nt][0] + b0) * scale;
            float v1 = (acc[mt][nt][1] + b1) * scale;
            float v2 = (acc[mt][nt][2] + b0) * scale;
            float v3 = (acc[mt][nt][3] + b1) * scale;
            if (outTf32) {
                v0 = __uint_as_float(f2tf32(v0));
                v1 = __uint_as_float(f2tf32(v1));
                v2 = __uint_as_float(f2tf32(v2));
                v3 = __uint_as_float(f2tf32(v3));
            }
            *(float2*)(C + (size_t)row0 * N + col)       = make_float2(v0, v1);
            *(float2*)(C + (size_t)(row0 + 8) * N + col) = make_float2(v2, v3);
        }
    }
}

// ---------------- mma-based flash attention ----------------
// 128 threads / 4 warps; warp owns 16 query rows. Joint softmax over 576 keys
// (8 feats tiles w/ Qa, 1 inps tile w/ Qb). Inputs are tf32-bit floats.
#define APAD 68   // frag banks 4g+tg conflict-free
#define VPAD 72   // frag banks 8tg+g conflict-free

__global__ __launch_bounds__(128) void attn_mma_kernel(
    const float* __restrict__ Qa, const float* __restrict__ Qb,
    const float* __restrict__ Kf, const float* __restrict__ Ki,
    const float* __restrict__ Vf, const float* __restrict__ Vi,
    const float* __restrict__ maskF, float* __restrict__ Out, int Tq)
{
    extern __shared__ unsigned smu[];
    unsigned* Qs = smu;                     // [64][APAD] tf32 [q][d]
    unsigned* Ks = Qs + 64 * APAD;          // [64][APAD] tf32 [key][d]
    unsigned* Vs = Ks + 64 * APAD;          // [64][VPAD] tf32 [key][e]
    unsigned* Ps = Vs + 64 * VPAD;          // [64][APAD] tf32 [q][key]
    float*    Ms = (float*)(Ps + 64 * APAD); // [TKC]

    const int tid  = threadIdx.x;
    const int wid  = tid >> 5;
    const int lane = tid & 31;
    const int g    = lane >> 2;
    const int tg   = lane & 3;
    const int wr   = wid * 16;

    const int qt = blockIdx.x, h = blockIdx.y, b = blockIdx.z;
    const int qBase = qt * 64;

    const float* Qa_p = Qa + ((size_t)b * Tq + qBase) * DC + h * EC;
    const float* Qb_p = Qb + ((size_t)b * Tq + qBase) * DC + h * EC;
    const float* Kf_p = Kf + (size_t)b * T1C * DC + h * EC;
    const float* Ki_p = Ki + (size_t)b * T2C * DC + h * EC;
    const float* Vf_p = Vf + (size_t)b * T1C * DC + h * EC;
    const float* Vi_p = Vi + (size_t)b * T2C * DC + h * EC;

    for (int i = tid; i < TKC; i += 128) Ms[i] = maskF[b * TKC + i];

    // load Qa (bit copy, already tf32)
    for (int i = tid; i < 64 * 16; i += 128) {
        int r = i >> 4, c = (i & 15) << 2;
        uint4 v = *(const uint4*)(Qa_p + (size_t)r * DC + c);
        *(uint4*)&Qs[r * APAD + c] = v;
    }

    float o[8][4];
#pragma unroll
    for (int et = 0; et < 8; et++)
#pragma unroll
        for (int r = 0; r < 4; r++) o[et][r] = 0.f;
    float mx0 = -CUDART_INF_F, mx1 = -CUDART_INF_F, l0 = 0.f, l1 = 0.f;

    for (int t = 0; t < 9; t++) {
        const float *Kp, *Vp;
        int keyBase;
        if (t < 8) { Kp = Kf_p + (size_t)t * 64 * DC; Vp = Vf_p + (size_t)t * 64 * DC; keyBase = t * 64; }
        else       { Kp = Ki_p;                       Vp = Vi_p;                       keyBase = T1C; }

        __syncthreads();   // previous tile's PV done before overwriting Ks/Vs (and Qs)
        if (t == 8) {
            for (int i = tid; i < 64 * 16; i += 128) {
                int r = i >> 4, c = (i & 15) << 2;
                uint4 v = *(const uint4*)(Qb_p + (size_t)r * DC + c);
                *(uint4*)&Qs[r * APAD + c] = v;
            }
        }
        for (int i = tid; i < 64 * 16; i += 128) {
            int r = i >> 4, c = (i & 15) << 2;
            uint4 kv = *(const uint4*)(Kp + (size_t)r * DC + c);
            *(uint4*)&Ks[r * APAD + c] = kv;
            uint4 vv = *(const uint4*)(Vp + (size_t)r * DC + c);
            *(uint4*)&Vs[r * VPAD + c] = vv;
        }
        __syncthreads();

        // S = Q @ K^T : warp computes 16x64
        float s[8][4];
#pragma unroll
        for (int nt = 0; nt < 8; nt++)
#pragma unroll
            for (int r = 0; r < 4; r++) s[nt][r] = 0.f;

#pragma unroll
        for (int ks = 0; ks < 64; ks += 8) {
            unsigned a0 = Qs[(wr + g) * APAD + ks + tg];
            unsigned a1 = Qs[(wr + g + 8) * APAD + ks + tg];
            unsigned a2 = Qs[(wr + g) * APAD + ks + tg + 4];
            unsigned a3 = Qs[(wr + g + 8) * APAD + ks + tg + 4];
#pragma unroll
            for (int nt = 0; nt < 8; nt++) {
                unsigned b0 = Ks[(nt * 8 + g) * APAD + ks + tg];
                unsigned b1 = Ks[(nt * 8 + g) * APAD + ks + tg + 4];
                MMA_TF32(s[nt], a0, a1, a2, a3, b0, b1);
            }
        }

        // mask (replace with -1e9) + row max
        float tm0 = -CUDART_INF_F, tm1 = -CUDART_INF_F;
#pragma unroll
        for (int nt = 0; nt < 8; nt++) {
            float mk0 = Ms[keyBase + nt * 8 + 2 * tg];
            float mk1 = Ms[keyBase + nt * 8 + 2 * tg + 1];
            if (mk0 != 0.f) { s[nt][0] = -1e9f; s[nt][2] = -1e9f; }
            if (mk1 != 0.f) { s[nt][1] = -1e9f; s[nt][3] = -1e9f; }
            tm0 = fmaxf(tm0, fmaxf(s[nt][0], s[nt][1]));
            tm1 = fmaxf(tm1, fmaxf(s[nt][2], s[nt][3]));
        }
        tm0 = fmaxf(tm0, __shfl_xor_sync(0xffffffffu, tm0, 1));
        tm0 = fmaxf(tm0, __shfl_xor_sync(0xffffffffu, tm0, 2));
        tm1 = fmaxf(tm1, __shfl_xor_sync(0xffffffffu, tm1, 1));
        tm1 = fmaxf(tm1, __shfl_xor_sync(0xffffffffu, tm1, 2));

        float mn0 = fmaxf(mx0, tm0), mn1 = fmaxf(mx1, tm1);
        float sc0 = __expf(mx0 - mn0), sc1 = __expf(mx1 - mn1);
        mx0 = mn0; mx1 = mn1;

        float rs0 = 0.f, rs1 = 0.f;
#pragma unroll
        for (int nt = 0; nt < 8; nt++) {
            s[nt][0] = __expf(s[nt][0] - mn0); rs0 += s[nt][0];
            s[nt][1] = __expf(s[nt][1] - mn0); rs0 += s[nt][1];
            s[nt][2] = __expf(s[nt][2] - mn1); rs1 += s[nt][2];
            s[nt][3] = __expf(s[nt][3] - mn1); rs1 += s[nt][3];
        }
        rs0 += __shfl_xor_sync(0xffffffffu, rs0, 1);
        rs0 += __shfl_xor_sync(0xffffffffu, rs0, 2);
        rs1 += __shfl_xor_sync(0xffffffffu, rs1, 1);
        rs1 += __shfl_xor_sync(0xffffffffu, rs1, 2);
        l0 = l0 * sc0 + rs0;
        l1 = l1 * sc1 + rs1;
#pragma unroll
        for (int et = 0; et < 8; et++) {
            o[et][0] *= sc0; o[et][1] *= sc0;
            o[et][2] *= sc1; o[et][3] *= sc1;
        }

        // write P (per-warp rows only -> warp-local sync suffices)
#pragma unroll
        for (int nt = 0; nt < 8; nt++) {
            uint2 p0 = make_uint2(f2tf32(s[nt][0]), f2tf32(s[nt][1]));
            uint2 p1 = make_uint2(f2tf32(s[nt][2]), f2tf32(s[nt][3]));
            *(uint2*)&Ps[(wr + g) * APAD + nt * 8 + 2 * tg]     = p0;
            *(uint2*)&Ps[(wr + g + 8) * APAD + nt * 8 + 2 * tg] = p1;
        }
        __syncwarp();

        // O += P @ V
#pragma unroll
        for (int ks = 0; ks < 64; ks += 8) {
            unsigned a0 = Ps[(wr + g) * APAD + ks + tg];
            unsigned a1 = Ps[(wr + g + 8) * APAD + ks + tg];
            unsigned a2 = Ps[(wr + g) * APAD + ks + tg + 4];
            unsigned a3 = Ps[(wr + g + 8) * APAD + ks + tg + 4];
#pragma unroll
            for (int et = 0; et < 8; et++) {
                unsigned b0 = Vs[(ks + tg) * VPAD + et * 8 + g];
                unsigned b1 = Vs[(ks + tg + 4) * VPAD + et * 8 + g];
                MMA_TF32(o[et], a0, a1, a2, a3, b0, b1);
            }
        }
    }

    // epilogue: normalize, write tf32-bit floats (feeds the tf32 out-proj GEMM)
    float inv0 = 1.f / l0, inv1 = 1.f / l1;
    int r0 = qBase + wr + g;
#pragma unroll
    for (int et = 0; et < 8; et++) {
        int col = h * EC + et * 8 + 2 * tg;
        uint2 v0 = make_uint2(f2tf32(o[et][0] * inv0), f2tf32(o[et][1] * inv0));
        uint2 v1 = make_uint2(f2tf32(o[et][2] * inv1), f2tf32(o[et][3] * inv1));
        *(uint2*)(Out + ((size_t)b * Tq + r0) * DC + col)     = v0;
        *(uint2*)(Out + ((size_t)b * Tq + r0 + 8) * DC + col) = v1;
    }
}

// ---------------- launch ----------------
extern "C" void kernel_launch(void* const* d_in, const int* in_sizes, int n_in,
                              void* d_out, int out_size)
{
    const float* feats = (const float*)d_in[0];
    const float* inps  = (const float*)d_in[1];
    const void*  amask = d_in[2];
    const float* W_f   = (const float*)d_in[3];
    const float* b_f   = (const float*)d_in[4];
    const float* W_i   = (const float*)d_in[5];
    const float* b_i   = (const float*)d_in[6];
    const float* Wu_v  = (const float*)d_in[7];
    const float* bu_v  = (const float*)d_in[8];
    const float* Wu_l  = (const float*)d_in[9];
    const float* bu_l  = (const float*)d_in[10];
    float* out = (float*)d_out;

    float *projF, *projI, *attV, *attL, *maskF;
    unsigned *featsT, *inpsT, *WfT, *WiT, *WuvT, *WulT;
    cudaGetSymbolAddress((void**)&projF, g_projF);
    cudaGetSymbolAddress((void**)&projI, g_projI);
    cudaGetSymbolAddress((void**)&attV,  g_attV);
    cudaGetSymbolAddress((void**)&attL,  g_attL);
    cudaGetSymbolAddress((void**)&maskF, g_maskF);
    cudaGetSymbolAddress((void**)&featsT, g_featsT);
    cudaGetSymbolAddress((void**)&inpsT,  g_inpsT);
    cudaGetSymbolAddress((void**)&WfT,  g_WfT);
    cudaGetSymbolAddress((void**)&WiT,  g_WiT);
    cudaGetSymbolAddress((void**)&WuvT, g_WuvT);
    cudaGetSymbolAddress((void**)&WulT, g_WulT);

    const size_t SF = (size_t)BB * T1C * DC;
    const size_t SI = (size_t)BB * T2C * DC;

    const int gemmSmem = (2 * GSM_A + 2 * GSM_B) * (int)sizeof(unsigned);          // 71680
    const int attnSmem = (3 * 64 * APAD + 64 * VPAD + TKC) * (int)sizeof(unsigned); // 72960
    cudaFuncSetAttribute(tf32gemm2_kernel, cudaFuncAttributeMaxDynamicSharedMemorySize, gemmSmem);
    cudaFuncSetAttribute(attn_mma_kernel,  cudaFuncAttributeMaxDynamicSharedMemorySize, attnSmem);

    // 1) mask + tf32 pre-conversion
    mask_prep_kernel<<<1, 256>>>((const unsigned*)amask, maskF);
    cvt_tf32_kernel<<<1024, 256>>>((const float4*)feats, (uint4*)featsT, (int)(SF / 4));
    cvt_tf32_kernel<<<256, 256>>>((const float4*)inps,  (uint4*)inpsT,  (int)(SI / 4));
    cvt_tf32_kernel<<<1024, 256>>>((const float4*)W_f,  (uint4*)WfT,  6 * DC * DC / 4);
    cvt_tf32_kernel<<<1024, 256>>>((const float4*)W_i,  (uint4*)WiT,  6 * DC * DC / 4);
    cvt_tf32_kernel<<<256, 256>>>((const float4*)Wu_v, (uint4*)WuvT, DC * DC / 4);
    cvt_tf32_kernel<<<256, 256>>>((const float4*)Wu_l, (uint4*)WulT, DC * DC / 4);

    // 2) projections (tf32 out), bias + E^-0.25 fused
    tf32gemm2_kernel<<<dim3(DC / 128, (BB * T1C) / 128, 6), 256, gemmSmem>>>(
        featsT, WfT, b_f, projF, BB * T1C, DC, DC, SCALE_P, 1);
    tf32gemm2_kernel<<<dim3(DC / 128, (BB * T2C) / 128, 6), 256, gemmSmem>>>(
        inpsT, WiT, b_i, projI, BB * T2C, DC, DC, SCALE_P, 1);

    // feats stack: [k_vv, q_vv, v_vv, q_lv, k_vl, v_vl]
    // inps  stack: [k_lv, v_lv, q_vl, q_ll, k_ll, v_ll]

    // 3) attention, both streams (outputs tf32-bit floats)
    attn_mma_kernel<<<dim3(T1C / 64, HC, BB), 128, attnSmem>>>(
        projF + 1 * SF, projF + 3 * SF,
        projF + 0 * SF, projI + 0 * SI,
        projF + 2 * SF, projI + 1 * SI,
        maskF, attV, T1C);
    attn_mma_kernel<<<dim3(T2C / 64, HC, BB), 128, attnSmem>>>(
        projI + 2 * SI, projI + 3 * SI,
        projF + 4 * SF, projI + 4 * SI,
        projF + 5 * SF, projI + 5 * SI,
        maskF, attL, T2C);

    // 4) output projections (fp32 out) into d_out: [out_v | out_l]
    tf32gemm2_kernel<<<dim3(DC / 128, (BB * T1C) / 128, 1), 256, gemmSmem>>>(
        (const unsigned*)attV, WuvT, bu_v, out, BB * T1C, DC, DC, 1.0f, 0);
    tf32gemm2_kernel<<<dim3(DC / 128, (BB * T2C) / 128, 1), 256, gemmSmem>>>(
        (const unsigned*)attL, WulT, bu_l, out + SF, BB * T2C, DC, DC, 1.0f, 0);
}